// round 1
// baseline (speedup 1.0000x reference)
#include <cuda_runtime.h>

#define BATCH 256
#define CH    2048
#define HW    196
#define NEXP  16
#define NA    3000
#define KDIM  2048

#define TN 256      // a-tile
#define TK 32       // k-tile
#define WP 36       // Ws pitch (pad for bank-conflict-free LDS.128)
#define AP 36
#define MAXTILES 64

__device__ float g_attended[BATCH * CH];
__device__ int   g_perm[BATCH];
__device__ int   g_tile_e[MAXTILES];
__device__ int   g_tile_m0[MAXTILES];
__device__ int   g_tile_cnt[MAXTILES];
__device__ int   g_numtiles;

// ---------------------------------------------------------------------------
// Kernel 1: masked weighted average pool.  grid (256, 8) x 256 threads.
// block = (b, channel-chunk of 256). Each warp handles 32 channels.
// ---------------------------------------------------------------------------
__global__ void pool_kernel(const float* __restrict__ mask,
                            const float* __restrict__ feat) {
    int b   = blockIdx.x;
    int tid = threadIdx.x;
    int wid = tid >> 5, lane = tid & 31;

    __shared__ __align__(16) float m_s[HW];
    __shared__ float warp_sum[8];
    __shared__ float s_inv;

    float v = 0.f;
    if (tid < HW) {
        v = mask[b * HW + tid] + 1e-10f;
        m_s[tid] = v;
    }
    #pragma unroll
    for (int o = 16; o > 0; o >>= 1) v += __shfl_down_sync(0xffffffffu, v, o);
    if (lane == 0) warp_sum[wid] = v;
    __syncthreads();
    if (tid == 0) {
        float s = 0.f;
        #pragma unroll
        for (int i = 0; i < 8; i++) s += warp_sum[i];
        s_inv = 1.0f / s;
    }
    __syncthreads();
    float inv = s_inv;

    const float4* m4 = (const float4*)m_s;   // 49 float4 = 196 floats exactly
    float4 mA = m4[lane];
    float4 mB = (lane < 17) ? m4[lane + 32] : make_float4(0.f, 0.f, 0.f, 0.f);

    int cbase = blockIdx.y * 256 + wid * 32;
    for (int it = 0; it < 32; it++) {
        int c = cbase + it;
        const float4* row = (const float4*)(feat + ((size_t)b * CH + c) * HW);
        float4 f = row[lane];
        float s = f.x * mA.x + f.y * mA.y + f.z * mA.z + f.w * mA.w;
        if (lane < 17) {
            float4 f2 = row[lane + 32];
            s += f2.x * mB.x + f2.y * mB.y + f2.z * mB.z + f2.w * mB.w;
        }
        #pragma unroll
        for (int o = 16; o > 0; o >>= 1) s += __shfl_down_sync(0xffffffffu, s, o);
        if (lane == 0) g_attended[b * CH + c] = s * inv;
    }
}

// ---------------------------------------------------------------------------
// Kernel 2: group batches by expert (stable), build M-tiles of 8.
// Also auto-detects int32 vs int64 inst dtype (JAX x64 ambiguity).
// Single block, 256 threads.
// ---------------------------------------------------------------------------
__global__ void group_kernel(const void* __restrict__ inst) {
    int tid = threadIdx.x;
    __shared__ int odd_nz;
    __shared__ int sh_e[BATCH];
    __shared__ int cnt[NEXP];
    __shared__ int off[NEXP + 1];

    if (tid == 0) odd_nz = 0;
    __syncthreads();
    const int* iv = (const int*)inst;
    // If dtype is int64 (LE), every odd 32-bit word is 0 (values are 0..15).
    // Only touch the first 256 int32 words (valid for both widths).
    if (tid < BATCH / 2 && iv[2 * tid + 1] != 0) atomicExch(&odd_nz, 1);
    __syncthreads();

    int e;
    if (odd_nz == 0) e = (int)((const long long*)inst)[tid];
    else             e = iv[tid];

    sh_e[tid] = e;
    if (tid < NEXP) cnt[tid] = 0;
    __syncthreads();

    atomicAdd(&cnt[e], 1);
    int rank = 0;
    for (int j = 0; j < tid; j++) rank += (sh_e[j] == e);
    __syncthreads();

    if (tid == 0) {
        off[0] = 0;
        for (int i = 0; i < NEXP; i++) off[i + 1] = off[i] + cnt[i];
        int nt = 0;
        for (int ei = 0; ei < NEXP; ei++)
            for (int s = 0; s < cnt[ei]; s += 8) {
                g_tile_e[nt]   = ei;
                g_tile_m0[nt]  = off[ei] + s;
                g_tile_cnt[nt] = min(8, cnt[ei] - s);
                nt++;
            }
        g_numtiles = nt;
    }
    __syncthreads();
    g_perm[off[e] + rank] = tid;
}

// ---------------------------------------------------------------------------
// Kernel 3: grouped GEMM.  out[bb, a] = attended[bb,:] . W[e, a, :] + bias[e,a]
// Block tile: M=8 (batches of one expert) x N=256 (a) x K=32, 128 threads.
// Microtile 4m x 4a, float4 along K (both smem operand layouts row-major,
// A-reads are broadcast, W-reads conflict-free with strided a-mapping).
// ---------------------------------------------------------------------------
__global__ __launch_bounds__(128)
void gemm_kernel(const float* __restrict__ W,
                 const float* __restrict__ bias,
                 float* __restrict__ out) {
    int tileid = blockIdx.y;
    if (tileid >= g_numtiles) return;

    int e    = g_tile_e[tileid];
    int m0   = g_tile_m0[tileid];
    int mcnt = g_tile_cnt[tileid];
    int a0   = blockIdx.x * TN;
    int tid  = threadIdx.x;

    __shared__ __align__(16) float As[8][AP];
    __shared__ __align__(16) float Ws[TN][WP];
    __shared__ int s_bb[8];

    if (tid < 8) s_bb[tid] = (tid < mcnt) ? g_perm[m0 + tid] : -1;
    __syncthreads();

    int tm = tid >> 6;      // 0..1  -> m rows tm*4 .. tm*4+3
    int ta = tid & 63;      // 0..63 -> a cols ta + 64*j

    float4 acc[4][4];
    #pragma unroll
    for (int r = 0; r < 4; r++)
        #pragma unroll
        for (int j = 0; j < 4; j++)
            acc[r][j] = make_float4(0.f, 0.f, 0.f, 0.f);

    const float* Wbase = W + (size_t)e * NA * KDIM;

    for (int k0 = 0; k0 < KDIM; k0 += TK) {
        // --- load A tile (8 x 32 floats = 64 float4, threads 0..63) ---
        if (tid < 64) {
            int row = tid >> 3, c4 = tid & 7;
            float4 v = make_float4(0.f, 0.f, 0.f, 0.f);
            int bb = s_bb[row];
            if (bb >= 0)
                v = *(const float4*)(g_attended + (size_t)bb * KDIM + k0 + c4 * 4);
            *(float4*)&As[row][c4 * 4] = v;
        }
        // --- load W tile (256 x 32 floats = 2048 float4, 16 per thread) ---
        #pragma unroll
        for (int i = 0; i < 16; i++) {
            int flat = tid + 128 * i;
            int row  = flat >> 3, c4 = flat & 7;
            float4 v = make_float4(0.f, 0.f, 0.f, 0.f);
            int a = a0 + row;
            if (a < NA)
                v = *(const float4*)(Wbase + (size_t)a * KDIM + k0 + c4 * 4);
            *(float4*)&Ws[row][c4 * 4] = v;
        }
        __syncthreads();

        #pragma unroll
        for (int kq = 0; kq < 8; kq++) {
            float4 a4[4], w4[4];
            #pragma unroll
            for (int r = 0; r < 4; r++)
                a4[r] = *(const float4*)&As[tm * 4 + r][kq * 4];
            #pragma unroll
            for (int j = 0; j < 4; j++)
                w4[j] = *(const float4*)&Ws[ta + 64 * j][kq * 4];
            #pragma unroll
            for (int r = 0; r < 4; r++)
                #pragma unroll
                for (int j = 0; j < 4; j++) {
                    acc[r][j].x = fmaf(a4[r].x, w4[j].x, acc[r][j].x);
                    acc[r][j].y = fmaf(a4[r].y, w4[j].y, acc[r][j].y);
                    acc[r][j].z = fmaf(a4[r].z, w4[j].z, acc[r][j].z);
                    acc[r][j].w = fmaf(a4[r].w, w4[j].w, acc[r][j].w);
                }
        }
        __syncthreads();
    }

    // --- epilogue: horizontal sum over k-lanes, add bias, scatter to out ---
    #pragma unroll
    for (int r = 0; r < 4; r++) {
        int m = tm * 4 + r;
        if (m < mcnt) {
            int bb = s_bb[m];
            #pragma unroll
            for (int j = 0; j < 4; j++) {
                int a = a0 + ta + 64 * j;
                if (a < NA) {
                    float s = acc[r][j].x + acc[r][j].y + acc[r][j].z + acc[r][j].w;
                    out[(size_t)bb * NA + a] = s + bias[e * NA + a];
                }
            }
        }
    }
}

// ---------------------------------------------------------------------------
extern "C" void kernel_launch(void* const* d_in, const int* in_sizes, int n_in,
                              void* d_out, int out_size) {
    const float* mask = (const float*)d_in[0];
    const float* feat = (const float*)d_in[1];
    const float* W    = (const float*)d_in[2];
    const float* bias = (const float*)d_in[3];
    const void*  inst = d_in[4];
    float* out = (float*)d_out;

    pool_kernel<<<dim3(BATCH, 8), 256>>>(mask, feat);
    group_kernel<<<1, BATCH>>>(inst);
    gemm_kernel<<<dim3((NA + TN - 1) / TN, MAXTILES), 128>>>(W, bias, out);
}

// round 2
// speedup vs baseline: 1.5324x; 1.5324x over previous
#include <cuda_runtime.h>

#define BATCH 256
#define CH    2048
#define HW    196
#define NEXP  16
#define NA    3000
#define KDIM  2048

#define MT    16          // batches per tile (b dimension)
#define BK    256         // attended k-tile
#define NKT   (KDIM/BK)   // 8 k-tiles
#define MAXTILES 32

__device__ float g_attended[BATCH * CH];
__device__ int   g_perm[BATCH];
__device__ int   g_tile_e[MAXTILES];
__device__ int   g_tile_m0[MAXTILES];
__device__ int   g_tile_cnt[MAXTILES];
__device__ int   g_numtiles;

// packed f32x2 FMA (FFMA2) — sm_103a only, ptxas never auto-fuses this
__device__ __forceinline__ unsigned long long fma2(unsigned long long a,
                                                   unsigned long long b,
                                                   unsigned long long c) {
    unsigned long long d;
    asm("fma.rn.f32x2 %0, %1, %2, %3;" : "=l"(d) : "l"(a), "l"(b), "l"(c));
    return d;
}
__device__ __forceinline__ float2 unpack2(unsigned long long v) {
    float2 f;
    asm("mov.b64 {%0,%1}, %2;" : "=f"(f.x), "=f"(f.y) : "l"(v));
    return f;
}

// ---------------------------------------------------------------------------
// Kernel 1: masked weighted average pool.  grid (256, 8) x 256 threads.
// ---------------------------------------------------------------------------
__global__ void pool_kernel(const float* __restrict__ mask,
                            const float* __restrict__ feat) {
    int b   = blockIdx.x;
    int tid = threadIdx.x;
    int wid = tid >> 5, lane = tid & 31;

    __shared__ __align__(16) float m_s[HW];
    __shared__ float warp_sum[8];
    __shared__ float s_inv;

    float v = 0.f;
    if (tid < HW) {
        v = mask[b * HW + tid] + 1e-10f;
        m_s[tid] = v;
    }
    #pragma unroll
    for (int o = 16; o > 0; o >>= 1) v += __shfl_down_sync(0xffffffffu, v, o);
    if (lane == 0) warp_sum[wid] = v;
    __syncthreads();
    if (tid == 0) {
        float s = 0.f;
        #pragma unroll
        for (int i = 0; i < 8; i++) s += warp_sum[i];
        s_inv = 1.0f / s;
    }
    __syncthreads();
    float inv = s_inv;

    const float4* m4 = (const float4*)m_s;
    float4 mA = m4[lane];
    float4 mB = (lane < 17) ? m4[lane + 32] : make_float4(0.f, 0.f, 0.f, 0.f);

    int cbase = blockIdx.y * 256 + wid * 32;
    for (int it = 0; it < 32; it++) {
        int c = cbase + it;
        const float4* row = (const float4*)(feat + ((size_t)b * CH + c) * HW);
        float4 f = row[lane];
        float s = f.x * mA.x + f.y * mA.y + f.z * mA.z + f.w * mA.w;
        if (lane < 17) {
            float4 f2 = row[lane + 32];
            s += f2.x * mB.x + f2.y * mB.y + f2.z * mB.z + f2.w * mB.w;
        }
        #pragma unroll
        for (int o = 16; o > 0; o >>= 1) s += __shfl_down_sync(0xffffffffu, s, o);
        if (lane == 0) g_attended[b * CH + c] = s * inv;
    }
}

// ---------------------------------------------------------------------------
// Kernel 2: group batches by expert (stable), build tiles of <=16.
// ---------------------------------------------------------------------------
__global__ void group_kernel(const void* __restrict__ inst) {
    int tid = threadIdx.x;
    __shared__ int odd_nz;
    __shared__ int sh_e[BATCH];
    __shared__ int cnt[NEXP];
    __shared__ int off[NEXP + 1];

    if (tid == 0) odd_nz = 0;
    __syncthreads();
    const int* iv = (const int*)inst;
    if (tid < BATCH / 2 && iv[2 * tid + 1] != 0) atomicExch(&odd_nz, 1);
    __syncthreads();

    int e;
    if (odd_nz == 0) e = (int)((const long long*)inst)[tid];
    else             e = iv[tid];

    sh_e[tid] = e;
    if (tid < NEXP) cnt[tid] = 0;
    __syncthreads();

    atomicAdd(&cnt[e], 1);
    int rank = 0;
    for (int j = 0; j < tid; j++) rank += (sh_e[j] == e);
    __syncthreads();

    if (tid == 0) {
        off[0] = 0;
        for (int i = 0; i < NEXP; i++) off[i + 1] = off[i] + cnt[i];
        int nt = 0;
        for (int ei = 0; ei < NEXP; ei++)
            for (int s = 0; s < cnt[ei]; s += MT) {
                g_tile_e[nt]   = ei;
                g_tile_m0[nt]  = off[ei] + s;
                g_tile_cnt[nt] = min(MT, cnt[ei] - s);
                nt++;
            }
        g_numtiles = nt;
    }
    __syncthreads();
    g_perm[off[e] + rank] = tid;
}

// ---------------------------------------------------------------------------
// Kernel 3: W-stationary grouped GEMM with FFMA2.
// Block: 256 thr (8 warps). Warp w owns 4 a-rows (a = ablock + w*4 + r).
// Lane l owns k-slice {4l..4l+3} of each 128-float segment.
// W: gmem->regs (read once, reused over 16 b in-thread).
// attended: smem double-buffered [2][MT][BK], reused over 32 a-rows.
// acc[r][b] is packed f32x2 k-partials; epilogue: horiz + lane butterfly.
// ---------------------------------------------------------------------------
__global__ __launch_bounds__(256, 1)
void gemm_kernel(const float* __restrict__ W,
                 const float* __restrict__ bias,
                 float* __restrict__ out) {
    int tileid = blockIdx.y;
    if (tileid >= g_numtiles) return;

    int e    = g_tile_e[tileid];
    int m0   = g_tile_m0[tileid];
    int mcnt = g_tile_cnt[tileid];
    int tid  = threadIdx.x;
    int wid  = tid >> 5, lane = tid & 31;
    int ablock = blockIdx.x * 32;

    __shared__ __align__(16) float att[2][MT][BK];
    __shared__ int s_bb[MT];

    if (tid < MT) s_bb[tid] = g_perm[m0 + min(tid, mcnt - 1)];
    __syncthreads();

    // ---- W row pointers (clamped; padded a-rows never written) ----
    const float* wrow[4];
    #pragma unroll
    for (int r = 0; r < 4; r++) {
        int a = ablock + wid * 4 + r;
        a = (a < NA) ? a : (NA - 1);
        wrow[r] = W + ((size_t)e * NA + a) * KDIM;
    }

    // ---- attended loader mapping: flat float4 f = tid + 256*i ----
    int l_row[4], l_c4[4];
    const float* l_src[4];
    #pragma unroll
    for (int i = 0; i < 4; i++) {
        int f = tid + 256 * i;
        l_row[i] = f >> 6;           // 64 float4 per row (BK=256)
        l_c4[i]  = f & 63;
        l_src[i] = g_attended + (size_t)s_bb[l_row[i]] * KDIM + l_c4[i] * 4;
    }

    // prefetch tile 0 and store
    float4 pre[4];
    #pragma unroll
    for (int i = 0; i < 4; i++) pre[i] = *(const float4*)(l_src[i]);
    #pragma unroll
    for (int i = 0; i < 4; i++)
        *(float4*)&att[0][l_row[i]][l_c4[i] * 4] = pre[i];
    __syncthreads();
    // prefetch tile 1 (regs)
    #pragma unroll
    for (int i = 0; i < 4; i++) pre[i] = *(const float4*)(l_src[i] + BK);

    unsigned long long acc[4][MT];
    #pragma unroll
    for (int r = 0; r < 4; r++)
        #pragma unroll
        for (int b = 0; b < MT; b++) acc[r][b] = 0ull;

    // W prefetch for first m-iter
    ulonglong2 wreg[4];
    #pragma unroll
    for (int r = 0; r < 4; r++)
        wreg[r] = *(const ulonglong2*)(wrow[r] + lane * 4);

    int buf = 0;
    // 16 m-iters: iter it covers k = it*128 + lane*4 .. +3 ; 2 iters per k-tile
    #pragma unroll 2
    for (int it = 0; it < 2 * NKT; it++) {
        // prefetch W for next iter
        ulonglong2 wnext[4];
        if (it + 1 < 2 * NKT) {
            int koff = (it + 1) * 128 + lane * 4;
            #pragma unroll
            for (int r = 0; r < 4; r++)
                wnext[r] = *(const ulonglong2*)(wrow[r] + koff);
        }
        // issue attended LDG for tile kt+2's first... (done at even it below)
        int kt = it >> 1;
        if ((it & 1) == 0 && kt + 2 <= NKT - 1) {
            // nothing: prefetch for kt+1 already in regs; issue kt+2 later
        }

        // compute from att[buf], segment (it&1)
        const float* base = &att[buf][0][(it & 1) * 128 + lane * 4];
        #pragma unroll
        for (int b = 0; b < MT; b++) {
            ulonglong2 t = *(const ulonglong2*)(base + b * BK);
            #pragma unroll
            for (int r = 0; r < 4; r++) {
                acc[r][b] = fma2(wreg[r].x, t.x, acc[r][b]);
                acc[r][b] = fma2(wreg[r].y, t.y, acc[r][b]);
            }
        }
        #pragma unroll
        for (int r = 0; r < 4; r++) wreg[r] = wnext[r];

        // at end of each k-tile: commit prefetched tile, fetch next
        if ((it & 1) == 1 && kt + 1 < NKT) {
            int nb = buf ^ 1;
            #pragma unroll
            for (int i = 0; i < 4; i++)
                *(float4*)&att[nb][l_row[i]][l_c4[i] * 4] = pre[i];
            __syncthreads();
            buf = nb;
            if (kt + 2 < NKT) {
                #pragma unroll
                for (int i = 0; i < 4; i++)
                    pre[i] = *(const float4*)(l_src[i] + (kt + 2) * BK);
            }
        }
    }

    // ---- epilogue: horizontal + butterfly reduce, scatter with bias ----
    float myval[2];
    myval[0] = 0.f; myval[1] = 0.f;
    #pragma unroll
    for (int r = 0; r < 4; r++) {
        #pragma unroll
        for (int b = 0; b < MT; b++) {
            float2 f = unpack2(acc[r][b]);
            float s = f.x + f.y;
            #pragma unroll
            for (int o = 16; o > 0; o >>= 1)
                s += __shfl_xor_sync(0xffffffffu, s, o);
            int v = r * MT + b;          // 0..63
            if ((v & 31) == lane) myval[v >> 5] = s;
        }
    }
    #pragma unroll
    for (int h = 0; h < 2; h++) {
        int v = lane + 32 * h;
        int r = v >> 4, b = v & 15;
        int a = ablock + wid * 4 + r;
        if (b < mcnt && a < NA) {
            out[(size_t)s_bb[b] * NA + a] = myval[h] + bias[e * NA + a];
        }
    }
}

// ---------------------------------------------------------------------------
extern "C" void kernel_launch(void* const* d_in, const int* in_sizes, int n_in,
                              void* d_out, int out_size) {
    const float* mask = (const float*)d_in[0];
    const float* feat = (const float*)d_in[1];
    const float* W    = (const float*)d_in[2];
    const float* bias = (const float*)d_in[3];
    const void*  inst = d_in[4];
    float* out = (float*)d_out;

    pool_kernel<<<dim3(BATCH, 8), 256>>>(mask, feat);
    group_kernel<<<1, BATCH>>>(inst);
    gemm_kernel<<<dim3((NA + 31) / 32, MAXTILES), 256>>>(W, bias, out);
}